// round 10
// baseline (speedup 1.0000x reference)
#include <cuda_runtime.h>

// Fixed problem shape
#define BB 4
#define CC 19
#define HH 256
#define WW 256
#define HW (HH * WW)
#define CHW (CC * HW)
#define RAD 10
#define TS 32
#define EW (TS + 2 * RAD)   // 52
#define NBLK 256            // 64 tiles x 4 images (no co-residency requirement)
#define RING (EW * EW - TS * TS)  // 1680 halo-ring pixels

// Device state: only tiny accumulators (self-resetting each replay)
__device__ int g_entmax[BB];     // entropy > 0 -> int atomicMax is order-preserving
__device__ double g_acc[BB][4];  // per-image: A=Σb·kl, B=Σb·kl·ent, C=Σb, D=Σb·ent
__device__ unsigned int g_done;  // finalize election

// ---------------------------------------------------------------------------
// Single kernel, NO grid sync: each block computes the fg halo ring itself
// (argmax needs only teacher loads + max chain; extra reads are L2 hits).
// ent/kl stay in registers; conf is linear in ent, so the per-image entropy
// max enters only the final scalar combine by the last-finishing block.
// ---------------------------------------------------------------------------
__global__ void __launch_bounds__(1024) ofkd_fused(
    const float* __restrict__ student, const float* __restrict__ teacher,
    float* __restrict__ out)
{
    const int b   = blockIdx.y;
    const int i0  = (blockIdx.x >> 3) * TS;
    const int j0  = (blockIdx.x & 7) * TS;
    const int tid = threadIdx.x;
    const int ty  = tid >> 5;          // tile row 0..31
    const int tx  = tid & 31;          // tile col 0..31

    __shared__ unsigned char sfg[EW][56];  // fg halo: col cc = global j0-10+cc
    __shared__ unsigned char svv[TS][56];  // vertical min-d^2

    const float* tbase = teacher + (size_t)b * CHW;

    // ---- fg ring: redundant argmax over the 1680 halo-ring pixels ----------
    for (int q = tid; q < RING; q += 1024) {
        int r, c;
        if (q < 520)       { r = q / 52;              c = q % 52; }
        else if (q < 1040) { r = 42 + (q - 520) / 52; c = (q - 520) % 52; }
        else {
            int k = q - 1040;
            r = 10 + k / 20;
            int c0 = k % 20;
            c = (c0 < 10) ? c0 : c0 + 32;
        }
        int gi = i0 - RAD + r, gj = j0 - RAD + c;
        unsigned char f = 0;
        if (gi >= 0 && gi < HH && gj >= 0 && gj < WW) {
            const float* tp = tbase + (size_t)gi * WW + gj;
            float t0 = __ldg(tp);
            float mx = __ldg(tp + HW);
#pragma unroll
            for (int cc = 2; cc < CC; cc++)
                mx = fmaxf(mx, __ldg(tp + (size_t)cc * HW));
            f = (mx > t0) ? 1 : 0;     // argmax != 0 (ties -> class 0)
        }
        sfg[r][c] = f;
    }

    // ---- phase A: channel math for own interior pixel ----------------------
    // t,s = logit/4.  Z=Σe^t, S=Σt e^t, T=Σs e^t, Zs=Σe^s
    // ent = logZ - S/Z ;  kl = (S-T)/Z - logZ + logZs
    float ent, kl;
    {
        const size_t base = (size_t)b * CHW + (size_t)(i0 + ty) * WW + (j0 + tx);
        const float* tp = teacher + base;
        const float* sp = student + base;

        float Z = 0.f, S = 0.f, Tt = 0.f, Zs = 0.f;
        float t0, mx = -1e30f;
#pragma unroll
        for (int c = 0; c < CC; c++) {
            float tv = __ldg(tp + (size_t)c * HW) * 0.25f;
            float sv = __ldg(sp + (size_t)c * HW) * 0.25f;
            float e = __expf(tv);
            Z += e;
            S = fmaf(e, tv, S);
            Tt = fmaf(e, sv, Tt);
            Zs += __expf(sv);
            if (c == 0) t0 = tv;
            else        mx = fmaxf(mx, tv);
        }
        const float lZ = __logf(Z);
        ent = lZ - S / Z;
        kl = (S - Tt) / Z - lZ + __logf(Zs);
        sfg[ty + RAD][tx + RAD] = (mx > t0) ? 1 : 0;

        // per-image entropy max (consumed only by the final scalar combine)
        float entm = ent;
#pragma unroll
        for (int o = 16; o > 0; o >>= 1)
            entm = fmaxf(entm, __shfl_xor_sync(0xFFFFFFFF, entm, o));
        __shared__ float smax[32];
        if ((tid & 31) == 0) smax[tid >> 5] = entm;
        __syncthreads();
        if (tid < 32) {
            float m = smax[tid];
#pragma unroll
            for (int o = 16; o > 0; o >>= 1)
                m = fmaxf(m, __shfl_xor_sync(0xFFFFFFFF, m, o));
            if (tid == 0) atomicMax(&g_entmax[b], __float_as_int(m));
        }
    }
    __syncthreads();   // sfg complete (ring + interior)

    // ---- vertical 21-tap min, byte SIMD (term = 200 - fg*(200-d^2)) --------
    if (tid < TS * 14) {
        int r = tid / 14, wc = (tid - r * 14) * 4;
        unsigned int va = 0xC8C8C8C8u, vb = 0xC8C8C8C8u;
#pragma unroll
        for (int dr = 0; dr < 21; dr += 2) {
            unsigned int f4 = *(const unsigned int*)&sfg[r + dr][wc];
            int d = dr - RAD;
            va = __vminu4(va, 0xC8C8C8C8u - f4 * (unsigned int)(200 - d * d));
        }
#pragma unroll
        for (int dr = 1; dr < 21; dr += 2) {
            unsigned int f4 = *(const unsigned int*)&sfg[r + dr][wc];
            int d = dr - RAD;
            vb = __vminu4(vb, 0xC8C8C8C8u - f4 * (unsigned int)(200 - d * d));
        }
        *(unsigned int*)&svv[r][wc] = __vminu4(va, vb);
    }
    __syncthreads();

    // ---- horizontal 21-tap min: independent byte-LDS, 3 split chains -------
    // pixel col tx -> smem cc = tx+10; taps cc-10..cc+10 = tx .. tx+20
    int m0 = 300, m1 = 300, m2 = 300;
#pragma unroll
    for (int s = 0; s < 7; s++) {
        int dd = s - RAD;
        m0 = min(m0, dd * dd + (int)svv[ty][tx + s]);
    }
#pragma unroll
    for (int s = 7; s < 14; s++) {
        int dd = s - RAD;
        m1 = min(m1, dd * dd + (int)svv[ty][tx + s]);
    }
#pragma unroll
    for (int s = 14; s < 21; s++) {
        int dd = s - RAD;
        m2 = min(m2, dd * dd + (int)svv[ty][tx + s]);
    }
    const int d2 = min(m0, min(m1, m2));

    // ---- base weight (conf folded in analytically at finalize) --------------
    float a0 = 0.f, a1 = 0.f, a2 = 0.f, a3 = 0.f;
    if (d2 <= RAD * RAD) {
        float wd = __expf((float)d2 * (-1.0f / 50.0f));   // 2*sigma^2 = 50
        float bnd = 0.f;
        if (sfg[ty + RAD][tx + RAD]) {
            bool er = sfg[ty + RAD - 1][tx + RAD] && sfg[ty + RAD + 1][tx + RAD]
                   && sfg[ty + RAD][tx + RAD - 1] && sfg[ty + RAD][tx + RAD + 1];
            if (!er) bnd = 1.f;
        }
        float bw = wd * (1.f + bnd);
        a0 = bw * kl;
        a1 = bw * kl * ent;
        a2 = bw;
        a3 = bw * ent;
    }

    // ---- block reduce 4 sums + fused finalize -------------------------------
#pragma unroll
    for (int o = 16; o > 0; o >>= 1) {
        a0 += __shfl_xor_sync(0xFFFFFFFF, a0, o);
        a1 += __shfl_xor_sync(0xFFFFFFFF, a1, o);
        a2 += __shfl_xor_sync(0xFFFFFFFF, a2, o);
        a3 += __shfl_xor_sync(0xFFFFFFFF, a3, o);
    }
    __shared__ float red[4][32];
    if ((tid & 31) == 0) {
        red[0][tid >> 5] = a0; red[1][tid >> 5] = a1;
        red[2][tid >> 5] = a2; red[3][tid >> 5] = a3;
    }
    __syncthreads();

    if (tid < 32) {
        float s0 = red[0][tid], s1 = red[1][tid], s2 = red[2][tid], s3 = red[3][tid];
#pragma unroll
        for (int o = 16; o > 0; o >>= 1) {
            s0 += __shfl_xor_sync(0xFFFFFFFF, s0, o);
            s1 += __shfl_xor_sync(0xFFFFFFFF, s1, o);
            s2 += __shfl_xor_sync(0xFFFFFFFF, s2, o);
            s3 += __shfl_xor_sync(0xFFFFFFFF, s3, o);
        }
        if (tid == 0) {
            atomicAdd(&g_acc[b][0], (double)s0);
            atomicAdd(&g_acc[b][1], (double)s1);
            atomicAdd(&g_acc[b][2], (double)s2);
            atomicAdd(&g_acc[b][3], (double)s3);
            __threadfence();
            unsigned int t = atomicAdd(&g_done, 1u);
            if (t == NBLK - 1) {   // last block: finalize + reset for next replay
                double num = 0.0, den = 0.0;
#pragma unroll
                for (int bb = 0; bb < BB; bb++) {
                    double Em = (double)__int_as_float(g_entmax[bb]) + 1e-8;
                    num += g_acc[bb][0] - 0.9 * g_acc[bb][1] / Em;
                    den += g_acc[bb][2] - 0.9 * g_acc[bb][3] / Em;
                    g_acc[bb][0] = 0.0; g_acc[bb][1] = 0.0;
                    g_acc[bb][2] = 0.0; g_acc[bb][3] = 0.0;
                    g_entmax[bb] = 0;
                }
                out[0] = (float)(16.0 * num / (den + 1e-8));
                atomicExch(&g_done, 0u);
            }
        }
    }
}

extern "C" void kernel_launch(void* const* d_in, const int* in_sizes, int n_in,
                              void* d_out, int out_size)
{
    const float* student = (const float*)d_in[0];
    const float* teacher = (const float*)d_in[1];
    float* out = (float*)d_out;

    ofkd_fused<<<dim3(64, BB), 1024>>>(student, teacher, out);
}